// round 2
// baseline (speedup 1.0000x reference)
#include <cuda_runtime.h>
#include <math.h>

#define N      8192
#define INCH   256
#define OUTCH  64
#define TI     64     // rows per block in main kernel
#define TJ     32     // j-tile
#define NITER  128    // 4096 / TJ  (each half-block covers 4096 j)

// ---------------- device scratch (no cudaMalloc allowed) ----------------
__device__ float  g_Wh[N * OUTCH];
__device__ float  g_s1[N];
__device__ float  g_s2[N];
__device__ float  g_scal[4];          // M1, M2, L0
__device__ float4 g_ep[N];            // (E1_j, Eh_j, s2_j, 0)
__device__ float4 g_ar[N];            // (A1_i, Ah_i, -s1_i, 0)

// ---------------- packed f32x2 helpers ----------------
#define FMA2(d, a, b) asm("fma.rn.f32x2 %0, %1, %2, %0;" : "+l"(d) : "l"(a), "l"(b))
#define PACK_DUP(d, x) asm("mov.b64 %0, {%1, %1};" : "=l"(d) : "f"(x))
#define UNPACK2(lo, hi, v) asm("mov.b64 {%0, %1}, %2;" : "=f"(lo), "=f"(hi) : "l"(v))

// ================= K1: Wh = h @ W  (8192x256 @ 256x64) =================
__global__ __launch_bounds__(256) void wh_kernel(const float* __restrict__ h,
                                                 const float* __restrict__ W) {
    __shared__ float Ws[64 * 64];          // one K-chunk of W: [kk][col]
    const int t      = threadIdx.x;
    const int col    = t & 63;
    const int rowgrp = t >> 6;             // 0..3 -> 4 rows each
    const int i0     = blockIdx.x * 16;

    float acc[4] = {0.f, 0.f, 0.f, 0.f};

    for (int kc = 0; kc < 4; kc++) {
        __syncthreads();
        // stage 64x64 chunk of W
        float4*       wsv = reinterpret_cast<float4*>(Ws);
        const float4* wgv = reinterpret_cast<const float4*>(W + kc * 64 * 64);
        #pragma unroll
        for (int q = 0; q < 4; q++) wsv[t + 256 * q] = wgv[t + 256 * q];
        __syncthreads();

        #pragma unroll 4
        for (int kk = 0; kk < 64; kk += 4) {
            const int k = kc * 64 + kk;
            float w0 = Ws[(kk + 0) * 64 + col];
            float w1 = Ws[(kk + 1) * 64 + col];
            float w2 = Ws[(kk + 2) * 64 + col];
            float w3 = Ws[(kk + 3) * 64 + col];
            #pragma unroll
            for (int rr = 0; rr < 4; rr++) {
                const int r = i0 + rowgrp * 4 + rr;
                const float4 hv = *reinterpret_cast<const float4*>(h + (size_t)r * INCH + k);
                acc[rr] += hv.x * w0 + hv.y * w1 + hv.z * w2 + hv.w * w3;
            }
        }
    }
    #pragma unroll
    for (int rr = 0; rr < 4; rr++) {
        const int r = i0 + rowgrp * 4 + rr;
        g_Wh[(size_t)r * OUTCH + col] = acc[rr];
    }
}

// ================= K2: s1 = Wh@a1, s2 = Wh@a2 =================
__global__ __launch_bounds__(256) void s_kernel(const float* __restrict__ a) {
    const int wid  = threadIdx.x >> 5;
    const int lane = threadIdx.x & 31;
    const int i    = blockIdx.x * 8 + wid;
    const float v1 = g_Wh[(size_t)i * 64 + lane];
    const float v2 = g_Wh[(size_t)i * 64 + 32 + lane];
    float p1 = v1 * a[lane]      + v2 * a[32 + lane];
    float p2 = v1 * a[64 + lane] + v2 * a[96 + lane];
    #pragma unroll
    for (int o = 16; o; o >>= 1) {
        p1 += __shfl_xor_sync(0xffffffffu, p1, o);
        p2 += __shfl_xor_sync(0xffffffffu, p2, o);
    }
    if (lane == 0) { g_s1[i] = p1; g_s2[i] = p2; }
}

// ================= K3: global maxes + L0 =================
__global__ __launch_bounds__(1024) void reduce_kernel() {
    __shared__ float sm1[1024], sm2[1024];
    const int t = threadIdx.x;
    float m1 = -3.4e38f, m2 = -3.4e38f;
    for (int i = t; i < N; i += 1024) {
        m1 = fmaxf(m1, g_s1[i]);
        m2 = fmaxf(m2, g_s2[i]);
    }
    sm1[t] = m1; sm2[t] = m2;
    __syncthreads();
    for (int s = 512; s; s >>= 1) {
        if (t < s) {
            sm1[t] = fmaxf(sm1[t], sm1[t + s]);
            sm2[t] = fmaxf(sm2[t], sm2[t + s]);
        }
        __syncthreads();
    }
    if (t == 0) {
        const float M1 = sm1[0], M2 = sm2[0];
        const float X  = M1 + M2;
        const float L0 = (X >= 0.f) ? X : 0.5f * X;   // lrelu(Xmax): upper bound of logits
        g_scal[0] = M1; g_scal[1] = M2; g_scal[2] = L0;
    }
}

// ================= K4: per-node exp factors =================
// branch x>=0: w = A1_i * E1_j = exp(x - L0); branch x<0: w = Ah_i * Eh_j = exp(x/2 - L0)
__global__ __launch_bounds__(256) void epack_kernel() {
    const int i = blockIdx.x * 256 + threadIdx.x;
    if (i >= N) return;
    const float M1 = g_scal[0], M2 = g_scal[1], L0 = g_scal[2];
    const float X  = M1 + M2;
    const float shift1 = (X >= 0.f) ? 0.f : 0.5f * X;   // makes A1*E1 = exp(x - L0)
    const float s1 = g_s1[i], s2 = g_s2[i];
    g_ar[i] = make_float4(expf(s1 - M1 + shift1), expf(0.5f * (s1 - L0)), -s1, 0.f);
    g_ep[i] = make_float4(expf(s2 - M2),          expf(0.5f * (s2 - L0)), s2,  0.f);
}

// ================= K5: fused mask + softmax + P@Wh + relu =================
// block: 256 thr = 2 groups of 128; group g covers j in [g*4096, (g+1)*4096)
// output tile: TI=64 rows x 64 cols; group-private packed-f32x2 accumulators,
// combined in smem at the end.
__global__ __launch_bounds__(256, 1) void gat_main(const int* __restrict__ adj,
                                                   float* __restrict__ out) {
    __shared__ __align__(16) float  w_s[2][TJ][TI];     // softmax weights tile
    __shared__ __align__(16) float  wh_s[2][TJ][64];    // Wh tile
    __shared__ float4 eps_s[2][2][TJ];                  // (E1,Eh,s2) double-buffered
    __shared__ float4 ar_s[TI];
    __shared__ float  Zs[256];

    const int t  = threadIdx.x;
    const int g  = t >> 7;          // 0/1: j-half
    const int lt = t & 127;
    const int i0 = blockIdx.x * TI;

    // phase-A mapping: one row, half of the j-tile per thread
    const int  ia    = lt & 63;
    const int  jh    = lt >> 6;                 // 0/1
    const long arow  = (long)(i0 + ia) * N;
    const int  jbase = g * 4096;

    // phase-B mapping: 8 rows x 4 cols of accumulators per thread
    const int cg = lt & 15, rg = lt >> 4;
    const int c0 = cg * 4, r0 = rg * 8;

    if (t < TI) ar_s[t] = g_ar[i0 + t];
    if (lt < TJ) eps_s[g][0][lt] = g_ep[jbase + lt];

    unsigned long long acc[4][4];   // [row-pair][col], packed f32x2
    #pragma unroll
    for (int p = 0; p < 4; p++)
        #pragma unroll
        for (int c = 0; c < 4; c++) acc[p][c] = 0ull;

    float Zpart = 0.f;

    // prefetch tile 0 (adj + Wh) into registers
    int4   adjv[4];
    float4 whv[4];
    {
        const int4* ap = reinterpret_cast<const int4*>(adj + arow + jbase + jh * 16);
        #pragma unroll
        for (int q = 0; q < 4; q++) adjv[q] = ap[q];
        const float4* wp = reinterpret_cast<const float4*>(g_Wh + (size_t)jbase * 64);
        #pragma unroll
        for (int q = 0; q < 4; q++) whv[q] = wp[lt + 128 * q];
    }

    __syncthreads();
    const float A1  = ar_s[ia].x;
    const float Ah  = ar_s[ia].y;
    const float ns1 = ar_s[ia].z;   // = -s1_i ; cond x>=0  <=>  s2_j >= ns1

    for (int it = 0; it < NITER; it++) {
        const int buf = it & 1;

        // ---- store Wh tile from prefetched regs ----
        float4* whsv = reinterpret_cast<float4*>(&wh_s[g][0][0]);
        #pragma unroll
        for (int q = 0; q < 4; q++) whsv[lt + 128 * q] = whv[q];

        // ---- compute softmax weights w for 16 (i,j) pairs ----
        #pragma unroll
        for (int q = 0; q < 4; q++) {
            const int4 av = adjv[q];
            const int mm[4] = {av.x, av.y, av.z, av.w};
            #pragma unroll
            for (int e = 0; e < 4; e++) {
                const int tj = jh * 16 + q * 4 + e;
                const float4 ep = eps_s[g][buf][tj];
                float w = (ep.z >= ns1) ? (A1 * ep.x) : (Ah * ep.y);
                w = (mm[e] != 0) ? w : 0.f;
                w_s[g][tj][ia] = w;
                Zpart += w;
            }
        }

        // stage exp factors for next tile (into the other buffer)
        if (it + 1 < NITER && lt < TJ)
            eps_s[g][buf ^ 1][lt] = g_ep[jbase + (it + 1) * TJ + lt];

        __syncthreads();

        // ---- prefetch next tile (latency hidden under FMA phase) ----
        if (it + 1 < NITER) {
            const int jnext = jbase + (it + 1) * TJ;
            const int4* ap = reinterpret_cast<const int4*>(adj + arow + jnext + jh * 16);
            #pragma unroll
            for (int q = 0; q < 4; q++) adjv[q] = ap[q];
            const float4* wp = reinterpret_cast<const float4*>(g_Wh + (size_t)jnext * 64);
            #pragma unroll
            for (int q = 0; q < 4; q++) whv[q] = wp[lt + 128 * q];
        }

        // ---- FMA phase: acc += w ⊗ Wh  (packed f32x2) ----
        #pragma unroll 8
        for (int tj = 0; tj < TJ; tj++) {
            const ulonglong2 w01 = *reinterpret_cast<const ulonglong2*>(&w_s[g][tj][r0]);
            const ulonglong2 w23 = *reinterpret_cast<const ulonglong2*>(&w_s[g][tj][r0 + 4]);
            const float4 wh = *reinterpret_cast<const float4*>(&wh_s[g][tj][c0]);
            const unsigned long long wpair[4] = {w01.x, w01.y, w23.x, w23.y};
            const float whc[4] = {wh.x, wh.y, wh.z, wh.w};
            #pragma unroll
            for (int c = 0; c < 4; c++) {
                unsigned long long b;
                PACK_DUP(b, whc[c]);
                #pragma unroll
                for (int p = 0; p < 4; p++) FMA2(acc[p][c], wpair[p], b);
            }
        }
        __syncthreads();
    }

    // ---- epilogue: combine groups, divide by Z, relu, store ----
    Zs[t] = Zpart;
    float* cb = &w_s[0][0][0];       // reuse as 64x64 combine buffer
    if (g == 1) {
        #pragma unroll
        for (int p = 0; p < 4; p++)
            #pragma unroll
            for (int c = 0; c < 4; c++) {
                float lo, hi;
                UNPACK2(lo, hi, acc[p][c]);
                cb[(r0 + 2 * p)     * 64 + (c0 + c)] = lo;
                cb[(r0 + 2 * p + 1) * 64 + (c0 + c)] = hi;
            }
    }
    __syncthreads();
    if (g == 0) {
        #pragma unroll
        for (int p = 0; p < 4; p++) {
            const int rA = r0 + 2 * p, rB = rA + 1;
            const float izA = 1.f / (Zs[rA] + Zs[rA + 64] + Zs[rA + 128] + Zs[rA + 192]);
            const float izB = 1.f / (Zs[rB] + Zs[rB + 64] + Zs[rB + 128] + Zs[rB + 192]);
            float vA[4], vB[4];
            #pragma unroll
            for (int c = 0; c < 4; c++) {
                float lo, hi;
                UNPACK2(lo, hi, acc[p][c]);
                lo += cb[rA * 64 + c0 + c];
                hi += cb[rB * 64 + c0 + c];
                vA[c] = fmaxf(lo * izA, 0.f);
                vB[c] = fmaxf(hi * izB, 0.f);
            }
            *reinterpret_cast<float4*>(out + (size_t)(i0 + rA) * 64 + c0) =
                make_float4(vA[0], vA[1], vA[2], vA[3]);
            *reinterpret_cast<float4*>(out + (size_t)(i0 + rB) * 64 + c0) =
                make_float4(vB[0], vB[1], vB[2], vB[3]);
        }
    }
}

// ================= launch =================
extern "C" void kernel_launch(void* const* d_in, const int* in_sizes, int n_in,
                              void* d_out, int out_size) {
    const float* h   = (const float*)d_in[0];
    const int*   adj = (const int*)d_in[1];
    const float* W   = (const float*)d_in[2];
    const float* a   = (const float*)d_in[3];
    float*       out = (float*)d_out;

    wh_kernel<<<N / 16, 256>>>(h, W);
    s_kernel<<<N / 8, 256>>>(a);
    reduce_kernel<<<1, 1024>>>();
    epack_kernel<<<N / 256, 256>>>();
    gat_main<<<N / TI, 256>>>(adj, out);
}

// round 3
// speedup vs baseline: 1.5520x; 1.5520x over previous
#include <cuda_runtime.h>
#include <math.h>

#define N      8192
#define INCH   256
#define OUTCH  64
#define TI     256            // rows per block (gat_main)
#define TJ     32             // j-tile
#define NSPLIT 4              // j-splits across blocks
#define JSPAN  (N / NSPLIT)   // 2048
#define NTILE  (JSPAN / TJ)   // 64

// ---------------- device scratch (no cudaMalloc allowed) ----------------
__device__ float    g_Wh[N * OUTCH];
__device__ float    g_s1[N];
__device__ float    g_s2[N];
__device__ float    g_scal[4];              // M1, M2, L0
__device__ float2   g_ep2[N];               // (E1_j, Eh_j)
__device__ float2   g_ar2[N];               // (A1_i, Ah_i)
__device__ unsigned g_adjT[(N / 32) * N];   // bit-packed adj, [word][row]
__device__ float    g_part[NSPLIT * N * OUTCH];
__device__ float    g_Zp[NSPLIT * N];

// ---------------- packed f32x2 helpers ----------------
#define FMA2(d, a, b) asm("fma.rn.f32x2 %0, %1, %2, %0;" : "+l"(d) : "l"(a), "l"(b))
#define PACK_DUP(d, x) asm("mov.b64 %0, {%1, %1};" : "=l"(d) : "f"(x))
#define UNPACK2(lo, hi, v) asm("mov.b64 {%0, %1}, %2;" : "=f"(lo), "=f"(hi) : "l"(v))

// ================= K0: bit-pack adjacency (transposed: [word][row]) =================
__global__ __launch_bounds__(1024) void bitpack_kernel(const int* __restrict__ adj) {
    __shared__ unsigned sw[32][33];
    const int wi = threadIdx.x >> 5, lane = threadIdx.x & 31;
    const int r0 = blockIdx.y * 32, w0 = blockIdx.x * 32;
    const int r = r0 + wi;
    const int* rowp = adj + (size_t)r * N + (size_t)w0 * 32;
    #pragma unroll
    for (int ww = 0; ww < 32; ww++) {
        const int v = rowp[ww * 32 + lane];
        const unsigned word = __ballot_sync(0xffffffffu, v != 0);
        if (lane == 0) sw[ww][wi] = word;
    }
    __syncthreads();
    // write coalesced: thread (wi, lane) writes word (w0+wi), row (r0+lane)
    g_adjT[(size_t)(w0 + wi) * N + r0 + lane] = sw[wi][lane];
}

// ================= K1: Wh = h @ W  (8192x256 @ 256x64) =================
__global__ __launch_bounds__(256) void wh_kernel(const float* __restrict__ h,
                                                 const float* __restrict__ W) {
    __shared__ float Ws[64 * 64];
    const int t = threadIdx.x;
    const int col = t & 63;
    const int rowgrp = t >> 6;
    const int i0 = blockIdx.x * 16;

    float acc[4] = {0.f, 0.f, 0.f, 0.f};
    for (int kc = 0; kc < 4; kc++) {
        __syncthreads();
        float4* wsv = reinterpret_cast<float4*>(Ws);
        const float4* wgv = reinterpret_cast<const float4*>(W + kc * 64 * 64);
        #pragma unroll
        for (int q = 0; q < 4; q++) wsv[t + 256 * q] = wgv[t + 256 * q];
        __syncthreads();

        #pragma unroll 4
        for (int kk = 0; kk < 64; kk += 4) {
            const int k = kc * 64 + kk;
            const float w0 = Ws[(kk + 0) * 64 + col];
            const float w1 = Ws[(kk + 1) * 64 + col];
            const float w2 = Ws[(kk + 2) * 64 + col];
            const float w3 = Ws[(kk + 3) * 64 + col];
            #pragma unroll
            for (int rr = 0; rr < 4; rr++) {
                const int rrow = i0 + rowgrp * 4 + rr;
                const float4 hv = *reinterpret_cast<const float4*>(h + (size_t)rrow * INCH + k);
                acc[rr] += hv.x * w0 + hv.y * w1 + hv.z * w2 + hv.w * w3;
            }
        }
    }
    #pragma unroll
    for (int rr = 0; rr < 4; rr++)
        g_Wh[(size_t)(i0 + rowgrp * 4 + rr) * OUTCH + col] = acc[rr];
}

// ================= K2: s1 = Wh@a1, s2 = Wh@a2 =================
__global__ __launch_bounds__(256) void s_kernel(const float* __restrict__ a) {
    const int wid = threadIdx.x >> 5;
    const int lane = threadIdx.x & 31;
    const int i = blockIdx.x * 8 + wid;
    const float v1 = g_Wh[(size_t)i * 64 + lane];
    const float v2 = g_Wh[(size_t)i * 64 + 32 + lane];
    float p1 = v1 * a[lane] + v2 * a[32 + lane];
    float p2 = v1 * a[64 + lane] + v2 * a[96 + lane];
    #pragma unroll
    for (int o = 16; o; o >>= 1) {
        p1 += __shfl_xor_sync(0xffffffffu, p1, o);
        p2 += __shfl_xor_sync(0xffffffffu, p2, o);
    }
    if (lane == 0) { g_s1[i] = p1; g_s2[i] = p2; }
}

// ================= K3: global maxes + L0 =================
__global__ __launch_bounds__(1024) void reduce_kernel() {
    __shared__ float sm1[1024], sm2[1024];
    const int t = threadIdx.x;
    float m1 = -3.4e38f, m2 = -3.4e38f;
    for (int i = t; i < N; i += 1024) {
        m1 = fmaxf(m1, g_s1[i]);
        m2 = fmaxf(m2, g_s2[i]);
    }
    sm1[t] = m1; sm2[t] = m2;
    __syncthreads();
    for (int s = 512; s; s >>= 1) {
        if (t < s) {
            sm1[t] = fmaxf(sm1[t], sm1[t + s]);
            sm2[t] = fmaxf(sm2[t], sm2[t + s]);
        }
        __syncthreads();
    }
    if (t == 0) {
        const float M1 = sm1[0], M2 = sm2[0];
        const float X = M1 + M2;
        g_scal[0] = M1; g_scal[1] = M2;
        g_scal[2] = (X >= 0.f) ? X : 0.5f * X;    // L0 = lrelu(max logit)
    }
}

// ================= K4: per-node exp factors =================
// w_ij = exp(lrelu(s1_i + s2_j) - L0) = max(A1_i*E1_j, Ah_i*Eh_j)
//   A1 = exp(s1-M1)        E1 = exp(s2-(L0-M1))
//   Ah = exp((s1-M1)/2)    Eh = exp(s2/2 - L0 + M1/2)
// all exponents <= 0 by construction -> no overflow.
__global__ __launch_bounds__(256) void epack_kernel() {
    const int i = blockIdx.x * 256 + threadIdx.x;
    if (i >= N) return;
    const float M1 = g_scal[0], L0 = g_scal[2];
    const float s1 = g_s1[i], s2 = g_s2[i];
    g_ar2[i] = make_float2(expf(s1 - M1), expf(0.5f * (s1 - M1)));
    g_ep2[i] = make_float2(expf(s2 - (L0 - M1)), expf(0.5f * s2 - L0 + 0.5f * M1));
}

// ================= K5: fused mask + weights + P@Wh (partial) =================
// block: 256 threads, tile TI=256 rows x 64 cols, covers JSPAN j's (1 of 4 splits).
// gen phase: thread t owns row (rowbase+t), computes 32 weights -> smem, accumulates Z.
// fma phase: thread owns 8 rows x 8 cols packed-f32x2 accumulators.
__global__ __launch_bounds__(256, 1) void gat_main() {
    extern __shared__ char smraw[];
    float*  w_s  = reinterpret_cast<float*>(smraw);                 // [TJ][TI] 32KB
    float*  wh_s = reinterpret_cast<float*>(smraw + TJ * TI * 4);   // [2][TJ][64] 16KB
    float2* ep_s = reinterpret_cast<float2*>(smraw + TJ * TI * 4 + 2 * TJ * 64 * 4); // [2][TJ]

    const int t = threadIdx.x;
    const int split = blockIdx.x, rowtile = blockIdx.y;
    const int rowbase = rowtile * TI;
    const int jbase = split * JSPAN;
    const int w0 = jbase / 32;

    const float2 ar = g_ar2[rowbase + t];
    const float A1 = ar.x, Ah = ar.y;

    const int rg = t >> 3, cg = t & 7;
    const int r0l = rg * 8;
    const int c0 = cg * 8;

    unsigned long long acc[8][4];
    #pragma unroll
    for (int r = 0; r < 8; r++)
        #pragma unroll
        for (int cp = 0; cp < 4; cp++) acc[r][cp] = 0ull;

    // prologue: stage tile 0 in buf0, prefetch tile 1
    {
        const float4* wp = reinterpret_cast<const float4*>(g_Wh + (size_t)jbase * 64);
        float4* ws = reinterpret_cast<float4*>(wh_s);
        ws[t * 2] = wp[t * 2];
        ws[t * 2 + 1] = wp[t * 2 + 1];
        if (t < TJ) ep_s[t] = g_ep2[jbase + t];
    }
    unsigned adj_cur = g_adjT[(size_t)w0 * N + rowbase + t];
    float4 whv0, whv1;
    float2 epv = make_float2(0.f, 0.f);
    unsigned adj_nxt;
    {
        const float4* wp = reinterpret_cast<const float4*>(g_Wh + (size_t)(jbase + TJ) * 64);
        whv0 = wp[t * 2];
        whv1 = wp[t * 2 + 1];
        if (t < TJ) epv = g_ep2[jbase + TJ + t];
        adj_nxt = g_adjT[(size_t)(w0 + 1) * N + rowbase + t];
    }
    __syncthreads();

    float Zl = 0.f;
    for (int it = 0; it < NTILE; it++) {
        const int buf = it & 1;
        const float* whb = wh_s + buf * TJ * 64;
        const float2* epb = ep_s + buf * TJ;

        // ---- gen phase: weights for this thread's row over 32 j ----
        {
            const unsigned word = adj_cur;
            #pragma unroll
            for (int tj = 0; tj < TJ; tj++) {
                const float2 e = epb[tj];
                const float v = fmaxf(A1 * e.x, Ah * e.y);
                const float w = ((word >> tj) & 1u) ? v : 0.f;
                w_s[tj * TI + t] = w;
                Zl += w;
            }
        }
        // stage next tile from prefetch regs (buf^1 was consumed last iteration)
        if (it + 1 < NTILE) {
            float4* ws = reinterpret_cast<float4*>(wh_s + (buf ^ 1) * TJ * 64);
            ws[t * 2] = whv0;
            ws[t * 2 + 1] = whv1;
            if (t < TJ) ep_s[(buf ^ 1) * TJ + t] = epv;
            adj_cur = adj_nxt;
        }
        __syncthreads();

        // prefetch tile it+2 (hidden under FMA phase)
        if (it + 2 < NTILE) {
            const int jn = jbase + (it + 2) * TJ;
            const float4* wp = reinterpret_cast<const float4*>(g_Wh + (size_t)jn * 64);
            whv0 = wp[t * 2];
            whv1 = wp[t * 2 + 1];
            if (t < TJ) epv = g_ep2[jn + t];
            adj_nxt = g_adjT[(size_t)(w0 + it + 2) * N + rowbase + t];
        }

        // ---- FMA phase: acc += w (8 rows) x wh (8 cols), packed along cols ----
        #pragma unroll 8
        for (int tj = 0; tj < TJ; tj++) {
            const float4 wa = *reinterpret_cast<const float4*>(w_s + tj * TI + r0l);
            const float4 wb = *reinterpret_cast<const float4*>(w_s + tj * TI + r0l + 4);
            const ulonglong2 hA = *reinterpret_cast<const ulonglong2*>(whb + tj * 64 + c0);
            const ulonglong2 hB = *reinterpret_cast<const ulonglong2*>(whb + tj * 64 + c0 + 4);
            const float wr[8] = {wa.x, wa.y, wa.z, wa.w, wb.x, wb.y, wb.z, wb.w};
            const unsigned long long hp[4] = {hA.x, hA.y, hB.x, hB.y};
            #pragma unroll
            for (int r = 0; r < 8; r++) {
                unsigned long long wd;
                PACK_DUP(wd, wr[r]);
                #pragma unroll
                for (int cp = 0; cp < 4; cp++) FMA2(acc[r][cp], wd, hp[cp]);
            }
        }
        __syncthreads();
    }

    // ---- epilogue: store Z and partial tile ----
    g_Zp[split * N + rowbase + t] = Zl;
    float* pb = g_part + ((size_t)split * N + rowbase) * 64;
    #pragma unroll
    for (int r = 0; r < 8; r++) {
        float o[8];
        #pragma unroll
        for (int cp = 0; cp < 4; cp++) UNPACK2(o[2 * cp], o[2 * cp + 1], acc[r][cp]);
        float* dst = pb + (size_t)(r0l + r) * 64 + c0;
        *reinterpret_cast<float4*>(dst) = make_float4(o[0], o[1], o[2], o[3]);
        *reinterpret_cast<float4*>(dst + 4) = make_float4(o[4], o[5], o[6], o[7]);
    }
}

// ================= K6: combine splits, normalize, relu =================
__global__ __launch_bounds__(256) void final_kernel(float* __restrict__ out) {
    const int idx = blockIdx.x * 256 + threadIdx.x;   // over 8192*16 float4s
    const int row = idx >> 4;
    const int c4 = idx & 15;
    const float z = g_Zp[row] + g_Zp[N + row] + g_Zp[2 * N + row] + g_Zp[3 * N + row];
    const float inv = 1.f / z;
    const size_t off = (size_t)row * 64 + c4 * 4;
    float4 s = *reinterpret_cast<const float4*>(g_part + off);
    #pragma unroll
    for (int sp = 1; sp < NSPLIT; sp++) {
        const float4 p = *reinterpret_cast<const float4*>(g_part + (size_t)sp * N * 64 + off);
        s.x += p.x; s.y += p.y; s.z += p.z; s.w += p.w;
    }
    *reinterpret_cast<float4*>(out + off) = make_float4(
        fmaxf(s.x * inv, 0.f), fmaxf(s.y * inv, 0.f),
        fmaxf(s.z * inv, 0.f), fmaxf(s.w * inv, 0.f));
}

// ================= launch =================
extern "C" void kernel_launch(void* const* d_in, const int* in_sizes, int n_in,
                              void* d_out, int out_size) {
    const float* h   = (const float*)d_in[0];
    const int*   adj = (const int*)d_in[1];
    const float* W   = (const float*)d_in[2];
    const float* a   = (const float*)d_in[3];
    float*       out = (float*)d_out;

    const int smem_main = TJ * TI * 4 + 2 * TJ * 64 * 4 + 2 * TJ * 8;  // 49664
    cudaFuncSetAttribute(gat_main, cudaFuncAttributeMaxDynamicSharedMemorySize, smem_main);

    bitpack_kernel<<<dim3(N / 1024, N / 32), 1024>>>(adj);
    wh_kernel<<<N / 16, 256>>>(h, W);
    s_kernel<<<N / 8, 256>>>(a);
    reduce_kernel<<<1, 1024>>>();
    epack_kernel<<<N / 256, 256>>>();
    gat_main<<<dim3(NSPLIT, N / TI), 256, smem_main>>>();
    final_kernel<<<(N * 16) / 256, 256>>>(out);
}

// round 5
// speedup vs baseline: 2.3825x; 1.5351x over previous
#include <cuda_runtime.h>
#include <cuda_bf16.h>
#include <math.h>
#include <stdint.h>

#define N      8192
#define INCH   256
#define OUTCH  64
#define NSPLIT 2
#define JSPAN  (N / NSPLIT)     // 4096
#define TIROWS 128
#define NH     (JSPAN / 32)     // 128 halves (32 j each)

// ---------------- device scratch ----------------
__device__ float    g_Wh[N * OUTCH];
__device__ float    g_s1[N], g_s2[N];
__device__ unsigned g_m1u, g_m2u;                 // encoded float max (idempotent)
__device__ __align__(16) float2 g_ep2[N];         // (E1_j, Eh_j)
__device__ float2   g_ar2[N];                     // (A1_i, Ah_i)
// B in mma-fragment layout: [kbg 0..511][nt 0..7][lane 0..31] x uint4(b0hi,b1hi,b0lo,b1lo)
__device__ uint4    g_Bfrag[(N / 16) * 8 * 32];
__device__ float    g_part[NSPLIT * N * OUTCH];
__device__ float    g_Zp[NSPLIT * N];

__device__ __forceinline__ unsigned fenc(float f) {
    unsigned u = __float_as_uint(f);
    return (u & 0x80000000u) ? ~u : (u | 0x80000000u);
}
__device__ __forceinline__ float fdec(unsigned k) {
    return __uint_as_float((k & 0x80000000u) ? (k ^ 0x80000000u) : ~k);
}
__device__ __forceinline__ uint32_t bf16x2_pack(float lo, float hi) {
    uint32_t r;
    asm("cvt.rn.bf16x2.f32 %0, %1, %2;" : "=r"(r) : "f"(hi), "f"(lo));  // upper=hi, lower=lo
    return r;
}

#define MMA16816(d, a0, a1, a2, a3, b0, b1)                                       \
    asm volatile("mma.sync.aligned.m16n8k16.row.col.f32.bf16.bf16.f32 "          \
        "{%0,%1,%2,%3}, {%4,%5,%6,%7}, {%8,%9}, {%0,%1,%2,%3};"                  \
        : "+f"((d)[0]), "+f"((d)[1]), "+f"((d)[2]), "+f"((d)[3])                  \
        : "r"(a0), "r"(a1), "r"(a2), "r"(a3), "r"(b0), "r"(b1))

// ================= K1: Wh = h @ W  + B-fragment (bf16 hi/lo) =================
__global__ __launch_bounds__(256) void wh_kernel(const float* __restrict__ h,
                                                 const float* __restrict__ W) {
    __shared__ float Ws[64 * 64];
    const int t = threadIdx.x;
    const int col = t & 63;             // n
    const int rowgrp = t >> 6;
    const int i0 = blockIdx.x * 16;     // 16 consecutive k (= one kbg)

    float acc[4] = {0.f, 0.f, 0.f, 0.f};
    for (int kc = 0; kc < 4; kc++) {
        __syncthreads();
        float4* wsv = reinterpret_cast<float4*>(Ws);
        const float4* wgv = reinterpret_cast<const float4*>(W + kc * 64 * 64);
        #pragma unroll
        for (int q = 0; q < 4; q++) wsv[t + 256 * q] = wgv[t + 256 * q];
        __syncthreads();

        #pragma unroll 4
        for (int kk = 0; kk < 64; kk += 4) {
            const int k = kc * 64 + kk;
            const float w0 = Ws[(kk + 0) * 64 + col];
            const float w1 = Ws[(kk + 1) * 64 + col];
            const float w2 = Ws[(kk + 2) * 64 + col];
            const float w3 = Ws[(kk + 3) * 64 + col];
            #pragma unroll
            for (int rr = 0; rr < 4; rr++) {
                const int rrow = i0 + rowgrp * 4 + rr;
                const float4 hv = *reinterpret_cast<const float4*>(h + (size_t)rrow * INCH + k);
                acc[rr] += hv.x * w0 + hv.y * w1 + hv.z * w2 + hv.w * w3;
            }
        }
    }
    #pragma unroll
    for (int rr = 0; rr < 4; rr++)
        g_Wh[(size_t)(i0 + rowgrp * 4 + rr) * OUTCH + col] = acc[rr];

    // write into mma B-fragment layout (k = row index, n = col)
    const int kbg = i0 >> 4;
    const int nt = col >> 3;
    const int g = col & 7;
    uint32_t* bf = reinterpret_cast<uint32_t*>(g_Bfrag);
    #pragma unroll
    for (int p = 0; p < 2; p++) {
        const int kp = rowgrp * 4 + 2 * p;              // even k-in-16 offset
        const int slotbase = (kp < 8) ? 0 : 1;          // b0 or b1
        const int tq = (kp < 8) ? (kp >> 1) : ((kp - 8) >> 1);
        const int lane = g * 4 + tq;
        const float vlo = acc[2 * p], vhi = acc[2 * p + 1];
        const uint32_t hiw = bf16x2_pack(vlo, vhi);
        const float rlo = vlo - __uint_as_float(hiw << 16);
        const float rhi = vhi - __uint_as_float(hiw & 0xffff0000u);
        const uint32_t low = bf16x2_pack(rlo, rhi);
        const size_t base = ((size_t)(kbg * 8 + nt) * 32 + lane) * 4;
        bf[base + slotbase] = hiw;
        bf[base + slotbase + 2] = low;
    }
}

// ================= K2: s1/s2 + encoded global max =================
__global__ __launch_bounds__(256) void s_kernel(const float* __restrict__ a) {
    __shared__ float sm1[8], sm2[8];
    const int wid = threadIdx.x >> 5;
    const int lane = threadIdx.x & 31;
    const int i = blockIdx.x * 8 + wid;
    const float v1 = g_Wh[(size_t)i * 64 + lane];
    const float v2 = g_Wh[(size_t)i * 64 + 32 + lane];
    float p1 = v1 * a[lane] + v2 * a[32 + lane];
    float p2 = v1 * a[64 + lane] + v2 * a[96 + lane];
    #pragma unroll
    for (int o = 16; o; o >>= 1) {
        p1 += __shfl_xor_sync(0xffffffffu, p1, o);
        p2 += __shfl_xor_sync(0xffffffffu, p2, o);
    }
    if (lane == 0) { g_s1[i] = p1; g_s2[i] = p2; sm1[wid] = p1; sm2[wid] = p2; }
    __syncthreads();
    if (threadIdx.x == 0) {
        float m1 = sm1[0], m2 = sm2[0];
        #pragma unroll
        for (int q = 1; q < 8; q++) { m1 = fmaxf(m1, sm1[q]); m2 = fmaxf(m2, sm2[q]); }
        atomicMax(&g_m1u, fenc(m1));
        atomicMax(&g_m2u, fenc(m2));
    }
}

// ================= K3: per-node exp factors =================
// w_ij = exp(lrelu(s1_i+s2_j) - L0) = max(A1_i*E1_j, Ah_i*Eh_j), exponents <= 0.
__global__ __launch_bounds__(256) void epack_kernel() {
    const int i = blockIdx.x * 256 + threadIdx.x;
    if (i >= N) return;
    const float M1 = fdec(g_m1u), M2 = fdec(g_m2u);
    const float X = M1 + M2;
    const float L0 = (X >= 0.f) ? X : 0.5f * X;
    const float s1 = g_s1[i], s2 = g_s2[i];
    g_ar2[i] = make_float2(expf(s1 - M1), expf(0.5f * (s1 - M1)));
    g_ep2[i] = make_float2(expf(s2 - (L0 - M1)), expf(0.5f * s2 - L0 + 0.5f * M1));
}

// ================= K4: fused mask+softmax-weights + mma.sync GEMM =================
// 256 thr = 8 warps; warp w owns rows [rowbase + 16w, +16). K-range = split's JSPAN,
// processed in 128 "halves" of 32 j. Weights generated straight into A fragments;
// adjacency read raw from adj (int32) — no bitpack pass.
#define LOAD_HALF(AJ, EP, HH) do {                                                \
    const int _j0 = jbase + (HH) * 32;                                            \
    _Pragma("unroll")                                                             \
    for (int _kb = 0; _kb < 2; _kb++) {                                           \
        _Pragma("unroll")                                                         \
        for (int _pr = 0; _pr < 2; _pr++) {                                       \
            const int _jo = _j0 + _kb * 16 + 2 * tq + _pr * 8;                    \
            EP[_kb][_pr] = *reinterpret_cast<const float4*>(&g_ep2[_jo]);         \
            AJ[_kb][0][_pr] = *reinterpret_cast<const int2*>(adj + (size_t)r1 * N + _jo); \
            AJ[_kb][1][_pr] = *reinterpret_cast<const int2*>(adj + (size_t)r2 * N + _jo); \
        }                                                                         \
    }                                                                             \
} while (0)

__global__ __launch_bounds__(256, 1) void gat_mma(const int* __restrict__ adj) {
    const int t = threadIdx.x;
    const int w = t >> 5, lane = t & 31;
    const int g = lane >> 2, tq = lane & 3;
    const int split = blockIdx.x;
    const int rowbase = blockIdx.y * TIROWS;
    const int jbase = split * JSPAN;
    const int kbg0 = jbase >> 4;

    const int r1 = rowbase + w * 16 + g;
    const int r2 = r1 + 8;
    const float2 ar1 = g_ar2[r1];
    const float2 ar2v = g_ar2[r2];

    float acc[8][4];
    #pragma unroll
    for (int nt = 0; nt < 8; nt++)
        #pragma unroll
        for (int c = 0; c < 4; c++) acc[nt][c] = 0.f;
    float Z1 = 0.f, Z2 = 0.f;

    int2  aj0[2][2][2], aj1[2][2][2];   // [kb][row01][pair]
    float4 ep0[2][2],   ep1[2][2];      // [kb][pair]
    LOAD_HALF(aj0, ep0, 0);
    LOAD_HALF(aj1, ep1, 1);

    for (int hh = 0; hh < NH; hh += 2) {
        #pragma unroll
        for (int sub = 0; sub < 2; sub++) {
            const int h = hh + sub;
            // compute on buffer sub
            #pragma unroll
            for (int kb = 0; kb < 2; kb++) {
                uint32_t ahi[4], alo[4];
                #pragma unroll
                for (int pr = 0; pr < 2; pr++) {
                    const float4 e = sub ? ep1[kb][pr] : ep0[kb][pr];
                    const int2 m1 = sub ? aj1[kb][0][pr] : aj0[kb][0][pr];
                    const int2 m2 = sub ? aj1[kb][1][pr] : aj0[kb][1][pr];
                    const float w1a = m1.x ? fmaxf(ar1.x * e.x, ar1.y * e.y) : 0.f;
                    const float w1b = m1.y ? fmaxf(ar1.x * e.z, ar1.y * e.w) : 0.f;
                    const float w2a = m2.x ? fmaxf(ar2v.x * e.x, ar2v.y * e.y) : 0.f;
                    const float w2b = m2.y ? fmaxf(ar2v.x * e.z, ar2v.y * e.w) : 0.f;
                    Z1 += w1a + w1b;
                    Z2 += w2a + w2b;
                    const uint32_t h1 = bf16x2_pack(w1a, w1b);
                    const uint32_t h2 = bf16x2_pack(w2a, w2b);
                    ahi[2 * pr + 0] = h1;
                    ahi[2 * pr + 1] = h2;
                    alo[2 * pr + 0] = bf16x2_pack(w1a - __uint_as_float(h1 << 16),
                                                  w1b - __uint_as_float(h1 & 0xffff0000u));
                    alo[2 * pr + 1] = bf16x2_pack(w2a - __uint_as_float(h2 << 16),
                                                  w2b - __uint_as_float(h2 & 0xffff0000u));
                }
                const int kbg = kbg0 + h * 2 + kb;
                const uint4* bp = g_Bfrag + ((size_t)kbg * 8) * 32 + lane;
                #pragma unroll
                for (int nt = 0; nt < 8; nt++) {
                    const uint4 b = bp[nt * 32];
                    MMA16816(acc[nt], ahi[0], ahi[1], ahi[2], ahi[3], b.x, b.y);
                    MMA16816(acc[nt], ahi[0], ahi[1], ahi[2], ahi[3], b.z, b.w);
                    MMA16816(acc[nt], alo[0], alo[1], alo[2], alo[3], b.x, b.y);
                }
            }
            // refill the buffer just consumed (prefetch 2 halves ahead)
            if (sub == 0) { if (hh + 2 < NH) LOAD_HALF(aj0, ep0, hh + 2); }
            else          { if (hh + 3 < NH) LOAD_HALF(aj1, ep1, hh + 3); }
        }
    }

    // Z reduce across the t-quad (lanes 4g+0..3)
    Z1 += __shfl_xor_sync(0xffffffffu, Z1, 1);
    Z1 += __shfl_xor_sync(0xffffffffu, Z1, 2);
    Z2 += __shfl_xor_sync(0xffffffffu, Z2, 1);
    Z2 += __shfl_xor_sync(0xffffffffu, Z2, 2);
    if (tq == 0) {
        g_Zp[split * N + r1] = Z1;
        g_Zp[split * N + r2] = Z2;
    }

    // store partial tile
    float* p1 = g_part + ((size_t)split * N + r1) * 64;
    float* p2 = g_part + ((size_t)split * N + r2) * 64;
    #pragma unroll
    for (int nt = 0; nt < 8; nt++) {
        const int c = nt * 8 + 2 * tq;
        *reinterpret_cast<float2*>(p1 + c) = make_float2(acc[nt][0], acc[nt][1]);
        *reinterpret_cast<float2*>(p2 + c) = make_float2(acc[nt][2], acc[nt][3]);
    }
}

// ================= K5: combine splits, normalize, relu =================
__global__ __launch_bounds__(256) void final_kernel(float* __restrict__ out) {
    const int idx = blockIdx.x * 256 + threadIdx.x;   // 8192*16 float4s
    const int row = idx >> 4;
    const int c4 = idx & 15;
    const float z = g_Zp[row] + g_Zp[N + row];
    const float inv = 1.f / z;
    const size_t off = (size_t)row * 64 + c4 * 4;
    float4 s = *reinterpret_cast<const float4*>(g_part + off);
    const float4 p = *reinterpret_cast<const float4*>(g_part + (size_t)N * 64 + off);
    s.x += p.x; s.y += p.y; s.z += p.z; s.w += p.w;
    *reinterpret_cast<float4*>(out + off) = make_float4(
        fmaxf(s.x * inv, 0.f), fmaxf(s.y * inv, 0.f),
        fmaxf(s.z * inv, 0.f), fmaxf(s.w * inv, 0.f));
}

// ================= launch =================
extern "C" void kernel_launch(void* const* d_in, const int* in_sizes, int n_in,
                              void* d_out, int out_size) {
    const float* h   = (const float*)d_in[0];
    const int*   adj = (const int*)d_in[1];
    const float* W   = (const float*)d_in[2];
    const float* a   = (const float*)d_in[3];
    float*       out = (float*)d_out;

    wh_kernel<<<N / 16, 256>>>(h, W);
    s_kernel<<<N / 8, 256>>>(a);
    epack_kernel<<<N / 256, 256>>>();
    gat_mma<<<dim3(NSPLIT, N / TIROWS), 256>>>(adj);
    final_kernel<<<(N * 16) / 256, 256>>>(out);
}